// round 4
// baseline (speedup 1.0000x reference)
#include <cuda_runtime.h>
#include <cuda_bf16.h>
#include <cstdint>
#include <cstddef>

#define S_LEN   2048
#define DMODEL  1024
#define NHEAD   16
#define DKHEAD  64
#define BATCH   2
#define M_ROWS  (BATCH * S_LEN)   /* 4096 */
#define NEGVAL  (-1.0e9f)

// ---------------------------------------------------------------------------
// Scratch (device globals: the sanctioned alloc-free scratch path)
// ---------------------------------------------------------------------------
__device__ float g_Q[(size_t)M_ROWS * DMODEL];
__device__ float g_K[(size_t)M_ROWS * DMODEL];
__device__ float g_V[(size_t)M_ROWS * DMODEL];
__device__ float g_O[(size_t)M_ROWS * DMODEL];
__device__ float g_S[(size_t)BATCH * NHEAD * S_LEN * S_LEN];  // scores / P in-place

// ---------------------------------------------------------------------------
// mma.sync helpers (baseline sm_80+ ISA, no 'a'-gated features)
// ---------------------------------------------------------------------------
__device__ __forceinline__ uint32_t smem_u32(const void* p) {
  uint32_t a;
  asm("{ .reg .u64 t; cvta.to.shared.u64 t, %1; cvt.u32.u64 %0, t; }"
      : "=r"(a) : "l"(p));
  return a;
}
__device__ __forceinline__ void ldmx4(uint32_t* r, uint32_t addr) {
  asm volatile("ldmatrix.sync.aligned.m8n8.x4.shared.b16 {%0,%1,%2,%3}, [%4];"
               : "=r"(r[0]), "=r"(r[1]), "=r"(r[2]), "=r"(r[3]) : "r"(addr));
}
__device__ __forceinline__ void mma16816(float* c, const uint32_t* a,
                                         const uint32_t* b) {
  asm volatile(
      "mma.sync.aligned.m16n8k16.row.col.f32.bf16.bf16.f32 "
      "{%0,%1,%2,%3}, {%4,%5,%6,%7}, {%8,%9}, {%0,%1,%2,%3};"
      : "+f"(c[0]), "+f"(c[1]), "+f"(c[2]), "+f"(c[3])
      : "r"(a[0]), "r"(a[1]), "r"(a[2]), "r"(a[3]), "r"(b[0]), "r"(b[1]));
}

// ---------------------------------------------------------------------------
// Tensor-core split-bf16 GEMM: C[4096x1024] = A[4096xK] @ W[1024xK]^T + bias
// D = AhBh + AhBl + AlBh accumulated in fp32 (residual ~2^-18).
// 128x128 CTA tile, 8 warps x (64x32), kc=32, padded smem (80B row stride:
// banks (20r+4u)%32 distinct for r=0..7 -> ldmatrix conflict-free).
// fp32 gmem loads are register-prefetched one chunk ahead; bf16 hi/lo split
// happens inline during the smem store.
// ---------------------------------------------------------------------------
#define KC     32
#define LDS_W  40   /* 32 data + 8 pad bf16 per row */

__global__ __launch_bounds__(256, 1) void gemm_mma(
    const float* __restrict__ A, const float* __restrict__ W,
    const float* __restrict__ bias, float* __restrict__ C) {
  __shared__ __nv_bfloat16 sAh[128 * LDS_W];
  __shared__ __nv_bfloat16 sAl[128 * LDS_W];
  __shared__ __nv_bfloat16 sBh[128 * LDS_W];
  __shared__ __nv_bfloat16 sBl[128 * LDS_W];

  const int tid = threadIdx.x;
  const int wid = tid >> 5;
  const int lane = tid & 31;
  const int r0 = blockIdx.y << 7;
  const int c0 = blockIdx.x << 7;
  const int mbase = (wid >> 2) << 6;   // 0 or 64
  const int nbase = (wid & 3) << 5;    // 0,32,64,96

  float acc[4][4][4];
#pragma unroll
  for (int i = 0; i < 4; ++i)
#pragma unroll
    for (int j = 0; j < 4; ++j)
#pragma unroll
      for (int t = 0; t < 4; ++t) acc[i][j][t] = 0.0f;

  // gmem load mapping: pass i: row = (tid>>3) + i*32, f4col = tid&7
  const int lrow = tid >> 3;
  const int lf4 = tid & 7;

  const uint32_t baseAh = smem_u32(sAh);
  const uint32_t baseAl = smem_u32(sAl);
  const uint32_t baseBh = smem_u32(sBh);
  const uint32_t baseBl = smem_u32(sBl);

  // ldmatrix per-thread address offsets (bytes)
  const uint32_t offA = (uint32_t)((lane & 15) * LDS_W + ((lane >> 4) << 3)) * 2;
  const uint32_t offB =
      (uint32_t)(((lane & 7) + ((lane >> 4) << 3)) * LDS_W + (((lane >> 3) & 1) << 3)) * 2;

  float4 ra[4], rw[4];
#pragma unroll
  for (int i = 0; i < 4; ++i) {
    ra[i] = *(const float4*)(A + (size_t)(r0 + lrow + i * 32) * DMODEL + lf4 * 4);
    rw[i] = *(const float4*)(W + (size_t)(c0 + lrow + i * 32) * DMODEL + lf4 * 4);
  }

  const uint32_t stoff = (uint32_t)(lrow * LDS_W + lf4 * 4);  // elt index (pass i adds 32 rows)

  for (int c = 0; c < DMODEL / KC; ++c) {
    __syncthreads();
#pragma unroll
    for (int i = 0; i < 4; ++i) {
      const uint32_t o = stoff + (uint32_t)(i * 32 * LDS_W);
      __nv_bfloat16 hx = __float2bfloat16_rn(ra[i].x);
      __nv_bfloat16 hy = __float2bfloat16_rn(ra[i].y);
      __nv_bfloat16 hz = __float2bfloat16_rn(ra[i].z);
      __nv_bfloat16 hw = __float2bfloat16_rn(ra[i].w);
      *(__nv_bfloat162*)(sAh + o)     = __halves2bfloat162(hx, hy);
      *(__nv_bfloat162*)(sAh + o + 2) = __halves2bfloat162(hz, hw);
      *(__nv_bfloat162*)(sAl + o) = __floats2bfloat162_rn(
          ra[i].x - __bfloat162float(hx), ra[i].y - __bfloat162float(hy));
      *(__nv_bfloat162*)(sAl + o + 2) = __floats2bfloat162_rn(
          ra[i].z - __bfloat162float(hz), ra[i].w - __bfloat162float(hw));
      __nv_bfloat16 gx = __float2bfloat16_rn(rw[i].x);
      __nv_bfloat16 gy = __float2bfloat16_rn(rw[i].y);
      __nv_bfloat16 gz = __float2bfloat16_rn(rw[i].z);
      __nv_bfloat16 gw = __float2bfloat16_rn(rw[i].w);
      *(__nv_bfloat162*)(sBh + o)     = __halves2bfloat162(gx, gy);
      *(__nv_bfloat162*)(sBh + o + 2) = __halves2bfloat162(gz, gw);
      *(__nv_bfloat162*)(sBl + o) = __floats2bfloat162_rn(
          rw[i].x - __bfloat162float(gx), rw[i].y - __bfloat162float(gy));
      *(__nv_bfloat162*)(sBl + o + 2) = __floats2bfloat162_rn(
          rw[i].z - __bfloat162float(gz), rw[i].w - __bfloat162float(gw));
    }
    __syncthreads();

    if (c + 1 < DMODEL / KC) {
      const int kb = (c + 1) * KC;
#pragma unroll
      for (int i = 0; i < 4; ++i) {
        ra[i] = *(const float4*)(A + (size_t)(r0 + lrow + i * 32) * DMODEL + kb + lf4 * 4);
        rw[i] = *(const float4*)(W + (size_t)(c0 + lrow + i * 32) * DMODEL + kb + lf4 * 4);
      }
    }

#pragma unroll
    for (int ks = 0; ks < 2; ++ks) {
      uint32_t afh[4][4], afl[4][4], bfh[2][4], bfl[2][4];
#pragma unroll
      for (int tm = 0; tm < 4; ++tm) {
        const uint32_t rowoff = (uint32_t)((mbase + tm * 16) * LDS_W * 2 + ks * 32);
        ldmx4(afh[tm], baseAh + rowoff + offA);
        ldmx4(afl[tm], baseAl + rowoff + offA);
      }
#pragma unroll
      for (int g = 0; g < 2; ++g) {
        const uint32_t rowoff = (uint32_t)((nbase + g * 16) * LDS_W * 2 + ks * 32);
        ldmx4(bfh[g], baseBh + rowoff + offB);
        ldmx4(bfl[g], baseBl + rowoff + offB);
      }
#pragma unroll
      for (int tm = 0; tm < 4; ++tm)
#pragma unroll
        for (int tn = 0; tn < 4; ++tn) {
          const int g = tn >> 1, h = (tn & 1) << 1;
          mma16816(acc[tm][tn], afh[tm], &bfh[g][h]);
          mma16816(acc[tm][tn], afh[tm], &bfl[g][h]);
          mma16816(acc[tm][tn], afl[tm], &bfh[g][h]);
        }
    }
  }

  // Epilogue: acc -> gmem (+bias). Lane: group=lane>>2 row, tig=lane&3 colpair.
  const int grp = lane >> 2, tig = lane & 3;
#pragma unroll
  for (int tm = 0; tm < 4; ++tm) {
#pragma unroll
    for (int tn = 0; tn < 4; ++tn) {
      const int col = c0 + nbase + tn * 8 + tig * 2;
      const float bx = bias[col], by = bias[col + 1];
      const int row0 = r0 + mbase + tm * 16 + grp;
      float2 v0 = make_float2(acc[tm][tn][0] + bx, acc[tm][tn][1] + by);
      float2 v1 = make_float2(acc[tm][tn][2] + bx, acc[tm][tn][3] + by);
      *(float2*)(C + (size_t)row0 * DMODEL + col) = v0;
      *(float2*)(C + (size_t)(row0 + 8) * DMODEL + col) = v1;
    }
  }
}

// ---------------------------------------------------------------------------
// Kernel: scores[bh, i, j] = (Q_h[i,:] . K_h[j,:]) / 8, causal-masked to NEG.
// ---------------------------------------------------------------------------
__global__ __launch_bounds__(256, 2) void mha_scores(
    const float* __restrict__ Qb, const float* __restrict__ Kb,
    float* __restrict__ Sc) {
  const int bh = blockIdx.z;
  const int b = bh >> 4, h = bh & 15;
  const int r0 = blockIdx.y << 7;
  const int c0 = blockIdx.x << 7;
  if (c0 > r0 + 127) return;

  const float* A  = Qb + (size_t)b * S_LEN * DMODEL + h * DKHEAD;
  const float* Wv = Kb + (size_t)b * S_LEN * DMODEL + h * DKHEAD;
  float* C = Sc + (size_t)bh * S_LEN * S_LEN;

  __shared__ float As[16][128];
  __shared__ float Bs[16][128];
  const int tid = threadIdx.x;
  const int tx = tid & 15, ty = tid >> 4;

  float acc[8][8];
#pragma unroll
  for (int i = 0; i < 8; ++i)
#pragma unroll
    for (int j = 0; j < 8; ++j) acc[i][j] = 0.0f;

  const int lrow = tid >> 2;
  const int lkc  = (tid & 3) << 2;
  const float* Ap = A  + (size_t)(r0 + lrow) * DMODEL + lkc;
  const float* Wp = Wv + (size_t)(c0 + lrow) * DMODEL + lkc;

  for (int k0 = 0; k0 < DKHEAD; k0 += 16) {
    float4 a0 = *(const float4*)(Ap + k0);
    float4 a1 = *(const float4*)(Ap + (size_t)64 * DMODEL + k0);
    float4 b0 = *(const float4*)(Wp + k0);
    float4 b1 = *(const float4*)(Wp + (size_t)64 * DMODEL + k0);
    __syncthreads();
    As[lkc + 0][lrow] = a0.x; As[lkc + 1][lrow] = a0.y;
    As[lkc + 2][lrow] = a0.z; As[lkc + 3][lrow] = a0.w;
    As[lkc + 0][lrow + 64] = a1.x; As[lkc + 1][lrow + 64] = a1.y;
    As[lkc + 2][lrow + 64] = a1.z; As[lkc + 3][lrow + 64] = a1.w;
    Bs[lkc + 0][lrow] = b0.x; Bs[lkc + 1][lrow] = b0.y;
    Bs[lkc + 2][lrow] = b0.z; Bs[lkc + 3][lrow] = b0.w;
    Bs[lkc + 0][lrow + 64] = b1.x; Bs[lkc + 1][lrow + 64] = b1.y;
    Bs[lkc + 2][lrow + 64] = b1.z; Bs[lkc + 3][lrow + 64] = b1.w;
    __syncthreads();
#pragma unroll
    for (int kk = 0; kk < 16; ++kk) {
      float ra[8], rb[8];
      *(float4*)(ra)     = *(const float4*)(&As[kk][ty * 8]);
      *(float4*)(ra + 4) = *(const float4*)(&As[kk][ty * 8 + 4]);
      *(float4*)(rb)     = *(const float4*)(&Bs[kk][tx * 8]);
      *(float4*)(rb + 4) = *(const float4*)(&Bs[kk][tx * 8 + 4]);
#pragma unroll
      for (int i = 0; i < 8; ++i)
#pragma unroll
        for (int j = 0; j < 8; ++j) acc[i][j] = fmaf(ra[i], rb[j], acc[i][j]);
    }
  }

#pragma unroll
  for (int i = 0; i < 8; ++i) {
    const int r = r0 + ty * 8 + i;
    float o[8];
#pragma unroll
    for (int j = 0; j < 8; ++j) {
      const int col = c0 + tx * 8 + j;
      float val = acc[i][j] * 0.125f;
      o[j] = (col > r) ? NEGVAL : val;
    }
    float* cp = C + (size_t)r * S_LEN + c0 + tx * 8;
    *(float4*)cp = make_float4(o[0], o[1], o[2], o[3]);
    *(float4*)(cp + 4) = make_float4(o[4], o[5], o[6], o[7]);
  }
}

// ---------------------------------------------------------------------------
// Kernel: row softmax, in place, over j in [0, diag-block-end).
// ---------------------------------------------------------------------------
__global__ __launch_bounds__(256) void mha_softmax(float* __restrict__ Sc) {
  const int i  = blockIdx.x;
  const int bh = blockIdx.y;
  float* row = Sc + ((size_t)bh * S_LEN + i) * S_LEN;
  const int jend = ((i >> 7) + 1) << 7;
  const int tid = threadIdx.x;

  float v[8];
  float mx = -3.0e38f;
#pragma unroll
  for (int u = 0; u < 8; ++u) {
    const int j = tid + (u << 8);
    v[u] = (j < jend) ? row[j] : -3.0e38f;
    mx = fmaxf(mx, v[u]);
  }

  __shared__ float sh[8];
#pragma unroll
  for (int o = 16; o > 0; o >>= 1) mx = fmaxf(mx, __shfl_xor_sync(0xffffffffu, mx, o));
  if ((tid & 31) == 0) sh[tid >> 5] = mx;
  __syncthreads();
  if (tid < 32) {
    float m2 = (tid < 8) ? sh[tid] : -3.0e38f;
#pragma unroll
    for (int o = 4; o > 0; o >>= 1) m2 = fmaxf(m2, __shfl_xor_sync(0xffffffffu, m2, o));
    if (tid == 0) sh[0] = m2;
  }
  __syncthreads();
  mx = sh[0];
  __syncthreads();

  float sm = 0.0f;
#pragma unroll
  for (int u = 0; u < 8; ++u) {
    v[u] = __expf(v[u] - mx);
    sm += v[u];
  }
#pragma unroll
  for (int o = 16; o > 0; o >>= 1) sm += __shfl_xor_sync(0xffffffffu, sm, o);
  if ((tid & 31) == 0) sh[tid >> 5] = sm;
  __syncthreads();
  if (tid < 32) {
    float s2 = (tid < 8) ? sh[tid] : 0.0f;
#pragma unroll
    for (int o = 4; o > 0; o >>= 1) s2 += __shfl_xor_sync(0xffffffffu, s2, o);
    if (tid == 0) sh[0] = s2;
  }
  __syncthreads();
  const float inv = 1.0f / sh[0];

#pragma unroll
  for (int u = 0; u < 8; ++u) {
    const int j = tid + (u << 8);
    if (j < jend) row[j] = v[u] * inv;
  }
}

// ---------------------------------------------------------------------------
// Kernel: O_h[128 x 64] = P[128 x kend] @ V_h[kend x 64], causal k-bound.
// ---------------------------------------------------------------------------
__global__ __launch_bounds__(256, 2) void mha_pv(
    const float* __restrict__ Sc, const float* __restrict__ Vb,
    float* __restrict__ Ob) {
  const int bh = blockIdx.y;
  const int b = bh >> 4, h = bh & 15;
  const int r0 = blockIdx.x << 7;

  const float* A  = Sc + (size_t)bh * S_LEN * S_LEN;
  const float* Bv = Vb + (size_t)b * S_LEN * DMODEL + h * DKHEAD;
  float* C = Ob + (size_t)b * S_LEN * DMODEL + h * DKHEAD;

  __shared__ float As[16][128];
  __shared__ float Bs[16][64];
  const int tid = threadIdx.x;
  const int tx = tid & 15, ty = tid >> 4;

  float acc[8][4];
#pragma unroll
  for (int i = 0; i < 8; ++i)
#pragma unroll
    for (int j = 0; j < 4; ++j) acc[i][j] = 0.0f;

  const int lrow = tid >> 2;
  const int lkc  = (tid & 3) << 2;
  const int bkrow = tid >> 4;
  const int bnc   = (tid & 15) << 2;
  const float* Ap = A + (size_t)(r0 + lrow) * S_LEN + lkc;
  const float* Bp = Bv + (size_t)bkrow * DMODEL + bnc;

  const int kend = r0 + 128;
  for (int k0 = 0; k0 < kend; k0 += 16) {
    float4 a0 = *(const float4*)(Ap + k0);
    float4 a1 = *(const float4*)(Ap + (size_t)64 * S_LEN + k0);
    float4 b0 = *(const float4*)(Bp + (size_t)k0 * DMODEL);
    __syncthreads();
    As[lkc + 0][lrow] = a0.x; As[lkc + 1][lrow] = a0.y;
    As[lkc + 2][lrow] = a0.z; As[lkc + 3][lrow] = a0.w;
    As[lkc + 0][lrow + 64] = a1.x; As[lkc + 1][lrow + 64] = a1.y;
    As[lkc + 2][lrow + 64] = a1.z; As[lkc + 3][lrow + 64] = a1.w;
    *(float4*)(&Bs[bkrow][bnc]) = b0;
    __syncthreads();
#pragma unroll
    for (int kk = 0; kk < 16; ++kk) {
      float ra[8];
      *(float4*)(ra)     = *(const float4*)(&As[kk][ty * 8]);
      *(float4*)(ra + 4) = *(const float4*)(&As[kk][ty * 8 + 4]);
      const float4 rb4 = *(const float4*)(&Bs[kk][tx * 4]);
      const float rb[4] = {rb4.x, rb4.y, rb4.z, rb4.w};
#pragma unroll
      for (int i = 0; i < 8; ++i)
#pragma unroll
        for (int j = 0; j < 4; ++j) acc[i][j] = fmaf(ra[i], rb[j], acc[i][j]);
    }
  }

#pragma unroll
  for (int i = 0; i < 8; ++i) {
    float* cp = C + (size_t)(r0 + ty * 8 + i) * DMODEL + tx * 4;
    *(float4*)cp = make_float4(acc[i][0], acc[i][1], acc[i][2], acc[i][3]);
  }
}

// ---------------------------------------------------------------------------
// Driver
// ---------------------------------------------------------------------------
extern "C" void kernel_launch(void* const* d_in, const int* in_sizes, int n_in,
                              void* d_out, int out_size) {
  (void)in_sizes; (void)n_in; (void)out_size;
  const float* q  = (const float*)d_in[0];
  const float* k  = (const float*)d_in[1];
  const float* v  = (const float*)d_in[2];
  // d_in[3] = mask: tril by construction; causal logic applied directly.
  const float* wq = (const float*)d_in[4];
  const float* bq = (const float*)d_in[5];
  const float* wk = (const float*)d_in[6];
  const float* bk = (const float*)d_in[7];
  const float* wv = (const float*)d_in[8];
  const float* bv = (const float*)d_in[9];
  const float* wo = (const float*)d_in[10];
  const float* bo = (const float*)d_in[11];
  float* out = (float*)d_out;

  float *pQ, *pK, *pV, *pO, *pS;
  cudaGetSymbolAddress((void**)&pQ, g_Q);
  cudaGetSymbolAddress((void**)&pK, g_K);
  cudaGetSymbolAddress((void**)&pV, g_V);
  cudaGetSymbolAddress((void**)&pO, g_O);
  cudaGetSymbolAddress((void**)&pS, g_S);

  const dim3 gproj(DMODEL / 128, M_ROWS / 128);   // (8, 32)
  gemm_mma<<<gproj, 256>>>(q, wq, bq, pQ);
  gemm_mma<<<gproj, 256>>>(k, wk, bk, pK);
  gemm_mma<<<gproj, 256>>>(v, wv, bv, pV);

  mha_scores<<<dim3(S_LEN / 128, S_LEN / 128, BATCH * NHEAD), 256>>>(pQ, pK, pS);
  mha_softmax<<<dim3(S_LEN, BATCH * NHEAD), 256>>>(pS);
  mha_pv<<<dim3(S_LEN / 128, BATCH * NHEAD), 256>>>(pS, pV, pO);

  gemm_mma<<<gproj, 256>>>(pO, wo, bo, out);
}

// round 5
// speedup vs baseline: 2.9145x; 2.9145x over previous
#include <cuda_runtime.h>
#include <cuda_bf16.h>
#include <cstdint>
#include <cstddef>

#define S_LEN   2048
#define DMODEL  1024
#define NHEAD   16
#define DKHEAD  64
#define BATCH   2
#define M_ROWS  (BATCH * S_LEN)   /* 4096 */

// ---------------------------------------------------------------------------
// Scratch (device globals: the sanctioned alloc-free scratch path)
// ---------------------------------------------------------------------------
__device__ float g_Q[(size_t)M_ROWS * DMODEL];
__device__ float g_K[(size_t)M_ROWS * DMODEL];
__device__ float g_V[(size_t)M_ROWS * DMODEL];
__device__ float g_O[(size_t)M_ROWS * DMODEL];

// ---------------------------------------------------------------------------
// mma.sync helpers (baseline sm_80+ ISA, no 'a'-gated features)
// ---------------------------------------------------------------------------
__device__ __forceinline__ uint32_t smem_u32(const void* p) {
  uint32_t a;
  asm("{ .reg .u64 t; cvta.to.shared.u64 t, %1; cvt.u32.u64 %0, t; }"
      : "=r"(a) : "l"(p));
  return a;
}
__device__ __forceinline__ void ldmx4(uint32_t* r, uint32_t addr) {
  asm volatile("ldmatrix.sync.aligned.m8n8.x4.shared.b16 {%0,%1,%2,%3}, [%4];"
               : "=r"(r[0]), "=r"(r[1]), "=r"(r[2]), "=r"(r[3]) : "r"(addr));
}
__device__ __forceinline__ void ldmx4t(uint32_t* r, uint32_t addr) {
  asm volatile("ldmatrix.sync.aligned.m8n8.x4.trans.shared.b16 {%0,%1,%2,%3}, [%4];"
               : "=r"(r[0]), "=r"(r[1]), "=r"(r[2]), "=r"(r[3]) : "r"(addr));
}
__device__ __forceinline__ void mma16816(float* c, const uint32_t* a,
                                         const uint32_t* b) {
  asm volatile(
      "mma.sync.aligned.m16n8k16.row.col.f32.bf16.bf16.f32 "
      "{%0,%1,%2,%3}, {%4,%5,%6,%7}, {%8,%9}, {%0,%1,%2,%3};"
      : "+f"(c[0]), "+f"(c[1]), "+f"(c[2]), "+f"(c[3])
      : "r"(a[0]), "r"(a[1]), "r"(a[2]), "r"(a[3]), "r"(b[0]), "r"(b[1]));
}
__device__ __forceinline__ uint32_t pack2(float x, float y) {
  __nv_bfloat162 t = __floats2bfloat162_rn(x, y);
  return *(uint32_t*)&t;
}
// split x,y into hi bf16x2 + lo residual bf16x2
__device__ __forceinline__ void split2(float x, float y, uint32_t& hi, uint32_t& lo) {
  __nv_bfloat16 hx = __float2bfloat16_rn(x);
  __nv_bfloat16 hy = __float2bfloat16_rn(y);
  __nv_bfloat162 h2 = __halves2bfloat162(hx, hy);
  hi = *(uint32_t*)&h2;
  lo = pack2(x - __bfloat162float(hx), y - __bfloat162float(hy));
}

// ---------------------------------------------------------------------------
// Tensor-core split-bf16 GEMM (projections): C = A @ W^T + bias  [R3, proven]
// ---------------------------------------------------------------------------
#define KC     32
#define LDS_W  40   /* 32 data + 8 pad bf16 per row */

__global__ __launch_bounds__(256, 1) void gemm_mma(
    const float* __restrict__ A, const float* __restrict__ W,
    const float* __restrict__ bias, float* __restrict__ C) {
  __shared__ __nv_bfloat16 sAh[128 * LDS_W];
  __shared__ __nv_bfloat16 sAl[128 * LDS_W];
  __shared__ __nv_bfloat16 sBh[128 * LDS_W];
  __shared__ __nv_bfloat16 sBl[128 * LDS_W];

  const int tid = threadIdx.x;
  const int wid = tid >> 5;
  const int lane = tid & 31;
  const int r0 = blockIdx.y << 7;
  const int c0 = blockIdx.x << 7;
  const int mbase = (wid >> 2) << 6;
  const int nbase = (wid & 3) << 5;

  float acc[4][4][4];
#pragma unroll
  for (int i = 0; i < 4; ++i)
#pragma unroll
    for (int j = 0; j < 4; ++j)
#pragma unroll
      for (int t = 0; t < 4; ++t) acc[i][j][t] = 0.0f;

  const int lrow = tid >> 3;
  const int lf4 = tid & 7;

  const uint32_t baseAh = smem_u32(sAh);
  const uint32_t baseAl = smem_u32(sAl);
  const uint32_t baseBh = smem_u32(sBh);
  const uint32_t baseBl = smem_u32(sBl);

  const uint32_t offA = (uint32_t)((lane & 15) * LDS_W + ((lane >> 4) << 3)) * 2;
  const uint32_t offB =
      (uint32_t)(((lane & 7) + ((lane >> 4) << 3)) * LDS_W + (((lane >> 3) & 1) << 3)) * 2;

  float4 ra[4], rw[4];
#pragma unroll
  for (int i = 0; i < 4; ++i) {
    ra[i] = *(const float4*)(A + (size_t)(r0 + lrow + i * 32) * DMODEL + lf4 * 4);
    rw[i] = *(const float4*)(W + (size_t)(c0 + lrow + i * 32) * DMODEL + lf4 * 4);
  }

  const uint32_t stoff = (uint32_t)(lrow * LDS_W + lf4 * 4);

  for (int c = 0; c < DMODEL / KC; ++c) {
    __syncthreads();
#pragma unroll
    for (int i = 0; i < 4; ++i) {
      const uint32_t o = stoff + (uint32_t)(i * 32 * LDS_W);
      uint32_t h0, l0, h1, l1;
      split2(ra[i].x, ra[i].y, h0, l0);
      split2(ra[i].z, ra[i].w, h1, l1);
      *(uint32_t*)(sAh + o) = h0; *(uint32_t*)(sAh + o + 2) = h1;
      *(uint32_t*)(sAl + o) = l0; *(uint32_t*)(sAl + o + 2) = l1;
      split2(rw[i].x, rw[i].y, h0, l0);
      split2(rw[i].z, rw[i].w, h1, l1);
      *(uint32_t*)(sBh + o) = h0; *(uint32_t*)(sBh + o + 2) = h1;
      *(uint32_t*)(sBl + o) = l0; *(uint32_t*)(sBl + o + 2) = l1;
    }
    __syncthreads();

    if (c + 1 < DMODEL / KC) {
      const int kb = (c + 1) * KC;
#pragma unroll
      for (int i = 0; i < 4; ++i) {
        ra[i] = *(const float4*)(A + (size_t)(r0 + lrow + i * 32) * DMODEL + kb + lf4 * 4);
        rw[i] = *(const float4*)(W + (size_t)(c0 + lrow + i * 32) * DMODEL + kb + lf4 * 4);
      }
    }

#pragma unroll
    for (int ks = 0; ks < 2; ++ks) {
      uint32_t afh[4][4], afl[4][4], bfh[2][4], bfl[2][4];
#pragma unroll
      for (int tm = 0; tm < 4; ++tm) {
        const uint32_t rowoff = (uint32_t)((mbase + tm * 16) * LDS_W * 2 + ks * 32);
        ldmx4(afh[tm], baseAh + rowoff + offA);
        ldmx4(afl[tm], baseAl + rowoff + offA);
      }
#pragma unroll
      for (int g = 0; g < 2; ++g) {
        const uint32_t rowoff = (uint32_t)((nbase + g * 16) * LDS_W * 2 + ks * 32);
        ldmx4(bfh[g], baseBh + rowoff + offB);
        ldmx4(bfl[g], baseBl + rowoff + offB);
      }
#pragma unroll
      for (int tm = 0; tm < 4; ++tm)
#pragma unroll
        for (int tn = 0; tn < 4; ++tn) {
          const int g = tn >> 1, h = (tn & 1) << 1;
          mma16816(acc[tm][tn], afh[tm], &bfh[g][h]);
          mma16816(acc[tm][tn], afh[tm], &bfl[g][h]);
          mma16816(acc[tm][tn], afl[tm], &bfh[g][h]);
        }
    }
  }

  const int grp = lane >> 2, tig = lane & 3;
#pragma unroll
  for (int tm = 0; tm < 4; ++tm) {
#pragma unroll
    for (int tn = 0; tn < 4; ++tn) {
      const int col = c0 + nbase + tn * 8 + tig * 2;
      const float bx = bias[col], by = bias[col + 1];
      const int row0 = r0 + mbase + tm * 16 + grp;
      float2 v0 = make_float2(acc[tm][tn][0] + bx, acc[tm][tn][1] + by);
      float2 v1 = make_float2(acc[tm][tn][2] + bx, acc[tm][tn][3] + by);
      *(float2*)(C + (size_t)row0 * DMODEL + col) = v0;
      *(float2*)(C + (size_t)(row0 + 8) * DMODEL + col) = v1;
    }
  }
}

// ---------------------------------------------------------------------------
// Fused flash attention (causal), split-bf16 mma.sync.
// Grid: (16 q-tiles [heavy first], 32 bh). 256 threads = 8 warps; warp w owns
// q-rows [w*16, w*16+16). S kept in registers; P re-packed to A-frags in regs.
// Smem: Q/K/V hi+lo tiles, 128 x 72 bf16 each (72 = 64 + 8 pad).
// ---------------------------------------------------------------------------
#define FD 72
#define TQH 0
#define TQL (128 * FD)
#define TKH (2 * 128 * FD)
#define TKL (3 * 128 * FD)
#define TVH (4 * 128 * FD)
#define TVL (5 * 128 * FD)
#define FLASH_SMEM (6 * 128 * FD * 2)   /* 110592 B */

__global__ __launch_bounds__(256, 1) void flash_attn(
    const float* __restrict__ Qg, const float* __restrict__ Kg,
    const float* __restrict__ Vg, float* __restrict__ Og) {
  extern __shared__ __nv_bfloat16 fsm[];
  const int bh = blockIdx.y;
  const int b = bh >> 4, h = bh & 15;
  const int qt = (int)gridDim.x - 1 - (int)blockIdx.x;   // heavy tiles first

  const int tid = threadIdx.x;
  const int wid = tid >> 5;
  const int lane = tid & 31;
  const int grp = lane >> 2, tig = lane & 3;

  const float* Qb = Qg + (size_t)b * S_LEN * DMODEL + h * DKHEAD;
  const float* Kb = Kg + (size_t)b * S_LEN * DMODEL + h * DKHEAD;
  const float* Vb = Vg + (size_t)b * S_LEN * DMODEL + h * DKHEAD;

  const int lrow16 = tid >> 4;    // 0..15 (row within 16-row pass)
  const int lf4 = tid & 15;       // 0..15 (float4 col: d = lf4*4)

  // ---- load Q tile, split into smem ----
#pragma unroll
  for (int p = 0; p < 8; ++p) {
    const int row = p * 16 + lrow16;
    float4 v = *(const float4*)(Qb + (size_t)(qt * 128 + row) * DMODEL + lf4 * 4);
    uint32_t h0, l0, h1, l1;
    split2(v.x, v.y, h0, l0);
    split2(v.z, v.w, h1, l1);
    const uint32_t o = (uint32_t)(row * FD + lf4 * 4);
    *(uint32_t*)(fsm + TQH + o) = h0; *(uint32_t*)(fsm + TQH + o + 2) = h1;
    *(uint32_t*)(fsm + TQL + o) = l0; *(uint32_t*)(fsm + TQL + o + 2) = l1;
  }
  __syncthreads();

  const uint32_t baseQh = smem_u32(fsm + TQH);
  const uint32_t baseQl = smem_u32(fsm + TQL);
  const uint32_t baseKh = smem_u32(fsm + TKH);
  const uint32_t baseKl = smem_u32(fsm + TKL);
  const uint32_t baseVh = smem_u32(fsm + TVH);
  const uint32_t baseVl = smem_u32(fsm + TVL);

  const uint32_t offA = (uint32_t)(wid * 16 * FD * 2) +
                        (uint32_t)((lane & 15) * FD + ((lane >> 4) << 3)) * 2;
  const uint32_t offB =
      (uint32_t)(((lane & 7) + ((lane >> 4) << 3)) * FD + (((lane >> 3) & 1) << 3)) * 2;
  const uint32_t offV =
      (uint32_t)(((lane & 7) + (((lane >> 3) & 1) << 3)) * FD + ((lane >> 4) << 3)) * 2;

  // ---- Q A-frags to registers (constant over k-tiles) ----
  uint32_t qh[4][4], ql[4][4];
#pragma unroll
  for (int kc = 0; kc < 4; ++kc) {
    ldmx4(qh[kc], baseQh + offA + kc * 32);
    ldmx4(ql[kc], baseQl + offA + kc * 32);
  }

  // ---- online softmax state + O accumulator ----
  float oacc[8][4];
#pragma unroll
  for (int f = 0; f < 8; ++f)
#pragma unroll
    for (int t = 0; t < 4; ++t) oacc[f][t] = 0.0f;
  float m0 = -1.0e30f, m1 = -1.0e30f, lsum0 = 0.0f, lsum1 = 0.0f;

  for (int kt = 0; kt <= qt; ++kt) {
    __syncthreads();   // previous iteration's compute done before overwrite
    // ---- load K,V tiles, split into smem ----
#pragma unroll
    for (int p = 0; p < 8; ++p) {
      const int row = p * 16 + lrow16;
      const size_t g = (size_t)(kt * 128 + row) * DMODEL + lf4 * 4;
      float4 vk = *(const float4*)(Kb + g);
      float4 vv = *(const float4*)(Vb + g);
      uint32_t h0, l0, h1, l1;
      const uint32_t o = (uint32_t)(row * FD + lf4 * 4);
      split2(vk.x, vk.y, h0, l0);
      split2(vk.z, vk.w, h1, l1);
      *(uint32_t*)(fsm + TKH + o) = h0; *(uint32_t*)(fsm + TKH + o + 2) = h1;
      *(uint32_t*)(fsm + TKL + o) = l0; *(uint32_t*)(fsm + TKL + o + 2) = l1;
      split2(vv.x, vv.y, h0, l0);
      split2(vv.z, vv.w, h1, l1);
      *(uint32_t*)(fsm + TVH + o) = h0; *(uint32_t*)(fsm + TVH + o + 2) = h1;
      *(uint32_t*)(fsm + TVL + o) = l0; *(uint32_t*)(fsm + TVL + o + 2) = l1;
    }
    __syncthreads();

    // ---- S = Q K^T (split x3) ----
    float sacc[16][4];
#pragma unroll
    for (int f = 0; f < 16; ++f)
#pragma unroll
      for (int t = 0; t < 4; ++t) sacc[f][t] = 0.0f;
#pragma unroll
    for (int kc = 0; kc < 4; ++kc) {
#pragma unroll
      for (int ng = 0; ng < 8; ++ng) {
        uint32_t kh4[4], kl4[4];
        const uint32_t bo = offB + (uint32_t)(ng * 16 * FD * 2) + kc * 32;
        ldmx4(kh4, baseKh + bo);
        ldmx4(kl4, baseKl + bo);
        mma16816(sacc[2 * ng], qh[kc], &kh4[0]);
        mma16816(sacc[2 * ng], qh[kc], &kl4[0]);
        mma16816(sacc[2 * ng], ql[kc], &kh4[0]);
        mma16816(sacc[2 * ng + 1], qh[kc], &kh4[2]);
        mma16816(sacc[2 * ng + 1], qh[kc], &kl4[2]);
        mma16816(sacc[2 * ng + 1], ql[kc], &kh4[2]);
      }
    }

    // ---- scale + causal mask (diag tile only) ----
    const bool diag = (kt == qt);
    const int row0 = wid * 16 + grp;       // local q row (t<2), +8 for t>=2
#pragma unroll
    for (int f = 0; f < 16; ++f) {
#pragma unroll
      for (int t = 0; t < 4; ++t) {
        float v = sacc[f][t] * 0.125f;
        if (diag) {
          const int col = f * 8 + tig * 2 + (t & 1);
          const int row = row0 + ((t >> 1) << 3);
          if (col > row) v = -1.0e30f;
        }
        sacc[f][t] = v;
      }
    }

    // ---- online softmax update ----
    float nm0 = m0, nm1 = m1;
#pragma unroll
    for (int f = 0; f < 16; ++f) {
      nm0 = fmaxf(nm0, fmaxf(sacc[f][0], sacc[f][1]));
      nm1 = fmaxf(nm1, fmaxf(sacc[f][2], sacc[f][3]));
    }
    nm0 = fmaxf(nm0, __shfl_xor_sync(0xffffffffu, nm0, 1));
    nm0 = fmaxf(nm0, __shfl_xor_sync(0xffffffffu, nm0, 2));
    nm1 = fmaxf(nm1, __shfl_xor_sync(0xffffffffu, nm1, 1));
    nm1 = fmaxf(nm1, __shfl_xor_sync(0xffffffffu, nm1, 2));
    const float a0 = __expf(m0 - nm0);
    const float a1 = __expf(m1 - nm1);
    m0 = nm0; m1 = nm1;
    lsum0 *= a0; lsum1 *= a1;
#pragma unroll
    for (int f = 0; f < 8; ++f) {
      oacc[f][0] *= a0; oacc[f][1] *= a0;
      oacc[f][2] *= a1; oacc[f][3] *= a1;
    }
    float rs0 = 0.0f, rs1 = 0.0f;
#pragma unroll
    for (int f = 0; f < 16; ++f) {
      sacc[f][0] = __expf(sacc[f][0] - m0);
      sacc[f][1] = __expf(sacc[f][1] - m0);
      sacc[f][2] = __expf(sacc[f][2] - m1);
      sacc[f][3] = __expf(sacc[f][3] - m1);
      rs0 += sacc[f][0] + sacc[f][1];
      rs1 += sacc[f][2] + sacc[f][3];
    }
    rs0 += __shfl_xor_sync(0xffffffffu, rs0, 1);
    rs0 += __shfl_xor_sync(0xffffffffu, rs0, 2);
    rs1 += __shfl_xor_sync(0xffffffffu, rs1, 1);
    rs1 += __shfl_xor_sync(0xffffffffu, rs1, 2);
    lsum0 += rs0; lsum1 += rs1;

    // ---- O += P V (P split x3, V via ldmatrix.trans) ----
#pragma unroll
    for (int kc2 = 0; kc2 < 8; ++kc2) {
      const float* f0 = sacc[2 * kc2];
      const float* f1 = sacc[2 * kc2 + 1];
      uint32_t ph[4], pl[4];
      split2(f0[0], f0[1], ph[0], pl[0]);
      split2(f0[2], f0[3], ph[1], pl[1]);
      split2(f1[0], f1[1], ph[2], pl[2]);
      split2(f1[2], f1[3], ph[3], pl[3]);
#pragma unroll
      for (int vg = 0; vg < 4; ++vg) {
        uint32_t vh4[4], vl4[4];
        const uint32_t vo = offV + (uint32_t)(kc2 * 16 * FD * 2) + vg * 32;
        ldmx4t(vh4, baseVh + vo);
        ldmx4t(vl4, baseVl + vo);
        mma16816(oacc[2 * vg], ph, &vh4[0]);
        mma16816(oacc[2 * vg], ph, &vl4[0]);
        mma16816(oacc[2 * vg], pl, &vh4[0]);
        mma16816(oacc[2 * vg + 1], ph, &vh4[2]);
        mma16816(oacc[2 * vg + 1], ph, &vl4[2]);
        mma16816(oacc[2 * vg + 1], pl, &vh4[2]);
      }
    }
  }

  // ---- epilogue: O /= l, store ----
  const float inv0 = 1.0f / lsum0;
  const float inv1 = 1.0f / lsum1;
  float* Ob = Og + (size_t)b * S_LEN * DMODEL + h * DKHEAD;
  const int gr0 = qt * 128 + wid * 16 + grp;
#pragma unroll
  for (int f = 0; f < 8; ++f) {
    const int col = f * 8 + tig * 2;
    *(float2*)(Ob + (size_t)gr0 * DMODEL + col) =
        make_float2(oacc[f][0] * inv0, oacc[f][1] * inv0);
    *(float2*)(Ob + (size_t)(gr0 + 8) * DMODEL + col) =
        make_float2(oacc[f][2] * inv1, oacc[f][3] * inv1);
  }
}

// ---------------------------------------------------------------------------
// Driver
// ---------------------------------------------------------------------------
extern "C" void kernel_launch(void* const* d_in, const int* in_sizes, int n_in,
                              void* d_out, int out_size) {
  (void)in_sizes; (void)n_in; (void)out_size;
  const float* q  = (const float*)d_in[0];
  const float* k  = (const float*)d_in[1];
  const float* v  = (const float*)d_in[2];
  // d_in[3] = mask: tril by construction; causal logic applied directly.
  const float* wq = (const float*)d_in[4];
  const float* bq = (const float*)d_in[5];
  const float* wk = (const float*)d_in[6];
  const float* bk = (const float*)d_in[7];
  const float* wv = (const float*)d_in[8];
  const float* bv = (const float*)d_in[9];
  const float* wo = (const float*)d_in[10];
  const float* bo = (const float*)d_in[11];
  float* out = (float*)d_out;

  float *pQ, *pK, *pV, *pO;
  cudaGetSymbolAddress((void**)&pQ, g_Q);
  cudaGetSymbolAddress((void**)&pK, g_K);
  cudaGetSymbolAddress((void**)&pV, g_V);
  cudaGetSymbolAddress((void**)&pO, g_O);

  cudaFuncSetAttribute(flash_attn, cudaFuncAttributeMaxDynamicSharedMemorySize,
                       FLASH_SMEM);

  const dim3 gproj(DMODEL / 128, M_ROWS / 128);   // (8, 32)
  gemm_mma<<<gproj, 256>>>(q, wq, bq, pQ);
  gemm_mma<<<gproj, 256>>>(k, wk, bk, pK);
  gemm_mma<<<gproj, 256>>>(v, wv, bv, pV);

  flash_attn<<<dim3(S_LEN / 128, BATCH * NHEAD), 256, FLASH_SMEM>>>(pQ, pK, pV, pO);

  gemm_mma<<<gproj, 256>>>(pO, wo, bo, out);
}

// round 7
// speedup vs baseline: 3.0583x; 1.0493x over previous
#include <cuda_runtime.h>
#include <cuda_bf16.h>
#include <cstdint>
#include <cstddef>

#define S_LEN   2048
#define DMODEL  1024
#define NHEAD   16
#define DKHEAD  64
#define BATCH   2
#define M_ROWS  (BATCH * S_LEN)   /* 4096 */

// ---------------------------------------------------------------------------
// Scratch (device globals: the sanctioned alloc-free scratch path)
// ---------------------------------------------------------------------------
__device__ float g_O[(size_t)M_ROWS * DMODEL];
// pre-split bf16 hi/lo Q,K,V (written directly by projection epilogues)
__device__ __align__(16) __nv_bfloat16 g_Qh[(size_t)M_ROWS * DMODEL];
__device__ __align__(16) __nv_bfloat16 g_Ql[(size_t)M_ROWS * DMODEL];
__device__ __align__(16) __nv_bfloat16 g_Kh[(size_t)M_ROWS * DMODEL];
__device__ __align__(16) __nv_bfloat16 g_Kl[(size_t)M_ROWS * DMODEL];
__device__ __align__(16) __nv_bfloat16 g_Vh[(size_t)M_ROWS * DMODEL];
__device__ __align__(16) __nv_bfloat16 g_Vl[(size_t)M_ROWS * DMODEL];

// ---------------------------------------------------------------------------
// mma.sync / cp.async helpers (baseline sm_80+ ISA, no 'a'-gated features)
// ---------------------------------------------------------------------------
__device__ __forceinline__ uint32_t smem_u32(const void* p) {
  uint32_t a;
  asm("{ .reg .u64 t; cvta.to.shared.u64 t, %1; cvt.u32.u64 %0, t; }"
      : "=r"(a) : "l"(p));
  return a;
}
__device__ __forceinline__ void ldmx4(uint32_t* r, uint32_t addr) {
  asm volatile("ldmatrix.sync.aligned.m8n8.x4.shared.b16 {%0,%1,%2,%3}, [%4];"
               : "=r"(r[0]), "=r"(r[1]), "=r"(r[2]), "=r"(r[3]) : "r"(addr));
}
__device__ __forceinline__ void ldmx4t(uint32_t* r, uint32_t addr) {
  asm volatile("ldmatrix.sync.aligned.m8n8.x4.trans.shared.b16 {%0,%1,%2,%3}, [%4];"
               : "=r"(r[0]), "=r"(r[1]), "=r"(r[2]), "=r"(r[3]) : "r"(addr));
}
__device__ __forceinline__ void mma16816(float* c, const uint32_t* a,
                                         const uint32_t* b) {
  asm volatile(
      "mma.sync.aligned.m16n8k16.row.col.f32.bf16.bf16.f32 "
      "{%0,%1,%2,%3}, {%4,%5,%6,%7}, {%8,%9}, {%0,%1,%2,%3};"
      : "+f"(c[0]), "+f"(c[1]), "+f"(c[2]), "+f"(c[3])
      : "r"(a[0]), "r"(a[1]), "r"(a[2]), "r"(a[3]), "r"(b[0]), "r"(b[1]));
}
__device__ __forceinline__ void cp16(uint32_t dst, const void* src) {
  asm volatile("cp.async.cg.shared.global [%0], [%1], 16;" :: "r"(dst), "l"(src));
}
__device__ __forceinline__ void cp_commit() {
  asm volatile("cp.async.commit_group;" ::: "memory");
}
__device__ __forceinline__ void cp_wait0() {
  asm volatile("cp.async.wait_group 0;" ::: "memory");
}
__device__ __forceinline__ uint32_t pack2(float x, float y) {
  __nv_bfloat162 t = __floats2bfloat162_rn(x, y);
  return *(uint32_t*)&t;
}
__device__ __forceinline__ void split2(float x, float y, uint32_t& hi, uint32_t& lo) {
  __nv_bfloat16 hx = __float2bfloat16_rn(x);
  __nv_bfloat16 hy = __float2bfloat16_rn(y);
  __nv_bfloat162 h2 = __halves2bfloat162(hx, hy);
  hi = *(uint32_t*)&h2;
  lo = pack2(x - __bfloat162float(hx), y - __bfloat162float(hy));
}

// ---------------------------------------------------------------------------
// Tensor-core split-bf16 GEMM: C = A @ W^T + bias.
// SPLIT_OUT=false: fp32 C.  SPLIT_OUT=true: bf16 hi/lo pair (Ch, Cl).
// ---------------------------------------------------------------------------
#define KC     32
#define LDS_W  40   /* 32 data + 8 pad bf16 per row */

template <bool SPLIT_OUT>
__global__ __launch_bounds__(256, 1) void gemm_mma(
    const float* __restrict__ A, const float* __restrict__ W,
    const float* __restrict__ bias, float* __restrict__ C,
    __nv_bfloat16* __restrict__ Ch, __nv_bfloat16* __restrict__ Cl) {
  __shared__ __nv_bfloat16 sAh[128 * LDS_W];
  __shared__ __nv_bfloat16 sAl[128 * LDS_W];
  __shared__ __nv_bfloat16 sBh[128 * LDS_W];
  __shared__ __nv_bfloat16 sBl[128 * LDS_W];

  const int tid = threadIdx.x;
  const int wid = tid >> 5;
  const int lane = tid & 31;
  const int r0 = blockIdx.y << 7;
  const int c0 = blockIdx.x << 7;
  const int mbase = (wid >> 2) << 6;
  const int nbase = (wid & 3) << 5;

  float acc[4][4][4];
#pragma unroll
  for (int i = 0; i < 4; ++i)
#pragma unroll
    for (int j = 0; j < 4; ++j)
#pragma unroll
      for (int t = 0; t < 4; ++t) acc[i][j][t] = 0.0f;

  const int lrow = tid >> 3;
  const int lf4 = tid & 7;

  const uint32_t baseAh = smem_u32(sAh);
  const uint32_t baseAl = smem_u32(sAl);
  const uint32_t baseBh = smem_u32(sBh);
  const uint32_t baseBl = smem_u32(sBl);

  const uint32_t offA = (uint32_t)((lane & 15) * LDS_W + ((lane >> 4) << 3)) * 2;
  const uint32_t offB =
      (uint32_t)(((lane & 7) + ((lane >> 4) << 3)) * LDS_W + (((lane >> 3) & 1) << 3)) * 2;

  float4 ra[4], rw[4];
#pragma unroll
  for (int i = 0; i < 4; ++i) {
    ra[i] = *(const float4*)(A + (size_t)(r0 + lrow + i * 32) * DMODEL + lf4 * 4);
    rw[i] = *(const float4*)(W + (size_t)(c0 + lrow + i * 32) * DMODEL + lf4 * 4);
  }

  const uint32_t stoff = (uint32_t)(lrow * LDS_W + lf4 * 4);

  for (int c = 0; c < DMODEL / KC; ++c) {
    __syncthreads();
#pragma unroll
    for (int i = 0; i < 4; ++i) {
      const uint32_t o = stoff + (uint32_t)(i * 32 * LDS_W);
      uint32_t h0, l0, h1, l1;
      split2(ra[i].x, ra[i].y, h0, l0);
      split2(ra[i].z, ra[i].w, h1, l1);
      *(uint32_t*)(sAh + o) = h0; *(uint32_t*)(sAh + o + 2) = h1;
      *(uint32_t*)(sAl + o) = l0; *(uint32_t*)(sAl + o + 2) = l1;
      split2(rw[i].x, rw[i].y, h0, l0);
      split2(rw[i].z, rw[i].w, h1, l1);
      *(uint32_t*)(sBh + o) = h0; *(uint32_t*)(sBh + o + 2) = h1;
      *(uint32_t*)(sBl + o) = l0; *(uint32_t*)(sBl + o + 2) = l1;
    }
    __syncthreads();

    if (c + 1 < DMODEL / KC) {
      const int kb = (c + 1) * KC;
#pragma unroll
      for (int i = 0; i < 4; ++i) {
        ra[i] = *(const float4*)(A + (size_t)(r0 + lrow + i * 32) * DMODEL + kb + lf4 * 4);
        rw[i] = *(const float4*)(W + (size_t)(c0 + lrow + i * 32) * DMODEL + kb + lf4 * 4);
      }
    }

#pragma unroll
    for (int ks = 0; ks < 2; ++ks) {
      uint32_t afh[4][4], afl[4][4], bfh[2][4], bfl[2][4];
#pragma unroll
      for (int tm = 0; tm < 4; ++tm) {
        const uint32_t rowoff = (uint32_t)((mbase + tm * 16) * LDS_W * 2 + ks * 32);
        ldmx4(afh[tm], baseAh + rowoff + offA);
        ldmx4(afl[tm], baseAl + rowoff + offA);
      }
#pragma unroll
      for (int g = 0; g < 2; ++g) {
        const uint32_t rowoff = (uint32_t)((nbase + g * 16) * LDS_W * 2 + ks * 32);
        ldmx4(bfh[g], baseBh + rowoff + offB);
        ldmx4(bfl[g], baseBl + rowoff + offB);
      }
#pragma unroll
      for (int tm = 0; tm < 4; ++tm)
#pragma unroll
        for (int tn = 0; tn < 4; ++tn) {
          const int g = tn >> 1, h = (tn & 1) << 1;
          mma16816(acc[tm][tn], afh[tm], &bfh[g][h]);
          mma16816(acc[tm][tn], afh[tm], &bfl[g][h]);
          mma16816(acc[tm][tn], afl[tm], &bfh[g][h]);
        }
    }
  }

  const int grp = lane >> 2, tig = lane & 3;
#pragma unroll
  for (int tm = 0; tm < 4; ++tm) {
#pragma unroll
    for (int tn = 0; tn < 4; ++tn) {
      const int col = c0 + nbase + tn * 8 + tig * 2;
      const float bx = bias[col], by = bias[col + 1];
      const int row0 = r0 + mbase + tm * 16 + grp;
      const float v00 = acc[tm][tn][0] + bx, v01 = acc[tm][tn][1] + by;
      const float v10 = acc[tm][tn][2] + bx, v11 = acc[tm][tn][3] + by;
      if (SPLIT_OUT) {
        uint32_t h0, l0, h1, l1;
        split2(v00, v01, h0, l0);
        split2(v10, v11, h1, l1);
        *(uint32_t*)(Ch + (size_t)row0 * DMODEL + col) = h0;
        *(uint32_t*)(Cl + (size_t)row0 * DMODEL + col) = l0;
        *(uint32_t*)(Ch + (size_t)(row0 + 8) * DMODEL + col) = h1;
        *(uint32_t*)(Cl + (size_t)(row0 + 8) * DMODEL + col) = l1;
      } else {
        *(float2*)(C + (size_t)row0 * DMODEL + col) = make_float2(v00, v01);
        *(float2*)(C + (size_t)(row0 + 8) * DMODEL + col) = make_float2(v10, v11);
      }
    }
  }
}

// ---------------------------------------------------------------------------
// Fused flash attention (causal), pre-split bf16 inputs, cp.async 2-stage pipe.
// Grid: (16 q-tiles [heavy first], 32 bh). 8 warps; warp w owns q-rows
// [w*16, w*16+16). Smem: Q(hi,lo) + 2 stages x K/V(hi,lo), 128x72 bf16 tiles.
// ---------------------------------------------------------------------------
#define FD 72
#define TILE_E   (128 * FD)            /* 9216 elts = 18432 B */
#define STG_E    (4 * TILE_E)          /* K hi,lo + V hi,lo */
#define SQH      0
#define SQL      TILE_E
#define SSTAGE   (2 * TILE_E)
#define FLASH_SMEM ((2 * TILE_E + 2 * STG_E) * 2)   /* 184320 B */

__global__ __launch_bounds__(256, 1) void flash_attn(
    const __nv_bfloat16* __restrict__ Qh, const __nv_bfloat16* __restrict__ Ql,
    const __nv_bfloat16* __restrict__ Kh, const __nv_bfloat16* __restrict__ Kl,
    const __nv_bfloat16* __restrict__ Vh, const __nv_bfloat16* __restrict__ Vl,
    float* __restrict__ Og) {
  extern __shared__ __nv_bfloat16 fsm[];
  const int bh = blockIdx.y;
  const int b = bh >> 4, h = bh & 15;
  const int qt = (int)gridDim.x - 1 - (int)blockIdx.x;   // heavy tiles first

  const int tid = threadIdx.x;
  const int wid = tid >> 5;
  const int lane = tid & 31;
  const int grp = lane >> 2, tig = lane & 3;

  const size_t hb = (size_t)b * S_LEN * DMODEL + h * DKHEAD;
  const __nv_bfloat16* Qhb = Qh + hb;
  const __nv_bfloat16* Qlb = Ql + hb;
  const __nv_bfloat16* Khb = Kh + hb;
  const __nv_bfloat16* Klb = Kl + hb;
  const __nv_bfloat16* Vhb = Vh + hb;
  const __nv_bfloat16* Vlb = Vl + hb;

  const uint32_t smem0 = smem_u32(fsm);

  // ---- issue Q loads (hi/lo), then stage-0 K/V loads ----
  // chunk mapping: idx = tid + j*256 -> row = idx>>3 (0..127), c8 = idx&7
#pragma unroll
  for (int j = 0; j < 4; ++j) {
    const int idx = tid + (j << 8);
    const int row = idx >> 3, c8 = idx & 7;
    const size_t g = (size_t)(qt * 128 + row) * DMODEL + c8 * 8;
    const uint32_t d = smem0 + (uint32_t)(row * FD + c8 * 8) * 2;
    cp16(d, Qhb + g);
    cp16(d + TILE_E * 2, Qlb + g);
  }
  cp_commit();
#pragma unroll
  for (int j = 0; j < 4; ++j) {
    const int idx = tid + (j << 8);
    const int row = idx >> 3, c8 = idx & 7;
    const size_t g = (size_t)(0 * 128 + row) * DMODEL + c8 * 8;
    const uint32_t d = smem0 + (uint32_t)(SSTAGE * 2) + (uint32_t)(row * FD + c8 * 8) * 2;
    cp16(d, Khb + g);
    cp16(d + TILE_E * 2, Klb + g);
    cp16(d + TILE_E * 4, Vhb + g);
    cp16(d + TILE_E * 6, Vlb + g);
  }
  cp_commit();
  cp_wait0();
  __syncthreads();

  const uint32_t offA = (uint32_t)(wid * 16 * FD * 2) +
                        (uint32_t)((lane & 15) * FD + ((lane >> 4) << 3)) * 2;
  const uint32_t offB =
      (uint32_t)(((lane & 7) + ((lane >> 4) << 3)) * FD + (((lane >> 3) & 1) << 3)) * 2;
  const uint32_t offV =
      (uint32_t)(((lane & 7) + (((lane >> 3) & 1) << 3)) * FD + ((lane >> 4) << 3)) * 2;

  // ---- Q A-frags to registers (constant over k-tiles) ----
  uint32_t qfh[4][4], qfl[4][4];
#pragma unroll
  for (int kc = 0; kc < 4; ++kc) {
    ldmx4(qfh[kc], smem0 + offA + kc * 32);
    ldmx4(qfl[kc], smem0 + TILE_E * 2 + offA + kc * 32);
  }

  float oacc[8][4];
#pragma unroll
  for (int f = 0; f < 8; ++f)
#pragma unroll
    for (int t = 0; t < 4; ++t) oacc[f][t] = 0.0f;
  float m0 = -1.0e30f, m1 = -1.0e30f, lsum0 = 0.0f, lsum1 = 0.0f;

  for (int kt = 0; kt <= qt; ++kt) {
    const int s = kt & 1;
    const uint32_t stg = smem0 + (uint32_t)((SSTAGE + s * STG_E) * 2);

    if (kt > 0) {
      cp_wait0();        // stage s data landed
      __syncthreads();   // all warps done with previous compute on this buffer
    }
    // prefetch stage s^1 for kt+1
    if (kt < qt) {
      const uint32_t nstg = smem0 + (uint32_t)((SSTAGE + (s ^ 1) * STG_E) * 2);
#pragma unroll
      for (int j = 0; j < 4; ++j) {
        const int idx = tid + (j << 8);
        const int row = idx >> 3, c8 = idx & 7;
        const size_t g = (size_t)((kt + 1) * 128 + row) * DMODEL + c8 * 8;
        const uint32_t d = nstg + (uint32_t)(row * FD + c8 * 8) * 2;
        cp16(d, Khb + g);
        cp16(d + TILE_E * 2, Klb + g);
        cp16(d + TILE_E * 4, Vhb + g);
        cp16(d + TILE_E * 6, Vlb + g);
      }
      cp_commit();
    }

    // ---- S = Q K^T (split x3) ----
    float sacc[16][4];
#pragma unroll
    for (int f = 0; f < 16; ++f)
#pragma unroll
      for (int t = 0; t < 4; ++t) sacc[f][t] = 0.0f;
#pragma unroll
    for (int kc = 0; kc < 4; ++kc) {
#pragma unroll
      for (int ng = 0; ng < 8; ++ng) {
        uint32_t kh4[4], kl4[4];
        const uint32_t bo = offB + (uint32_t)(ng * 16 * FD * 2) + kc * 32;
        ldmx4(kh4, stg + bo);
        ldmx4(kl4, stg + TILE_E * 2 + bo);
        mma16816(sacc[2 * ng], qfh[kc], &kh4[0]);
        mma16816(sacc[2 * ng], qfh[kc], &kl4[0]);
        mma16816(sacc[2 * ng], qfl[kc], &kh4[0]);
        mma16816(sacc[2 * ng + 1], qfh[kc], &kh4[2]);
        mma16816(sacc[2 * ng + 1], qfh[kc], &kl4[2]);
        mma16816(sacc[2 * ng + 1], qfl[kc], &kh4[2]);
      }
    }

    // ---- scale + causal mask (diag tile only) ----
    const bool diag = (kt == qt);
    const int row0 = wid * 16 + grp;
#pragma unroll
    for (int f = 0; f < 16; ++f) {
#pragma unroll
      for (int t = 0; t < 4; ++t) {
        float v = sacc[f][t] * 0.125f;
        if (diag) {
          const int col = f * 8 + tig * 2 + (t & 1);
          const int row = row0 + ((t >> 1) << 3);
          if (col > row) v = -1.0e30f;
        }
        sacc[f][t] = v;
      }
    }

    // ---- online softmax update ----
    float nm0 = m0, nm1 = m1;
#pragma unroll
    for (int f = 0; f < 16; ++f) {
      nm0 = fmaxf(nm0, fmaxf(sacc[f][0], sacc[f][1]));
      nm1 = fmaxf(nm1, fmaxf(sacc[f][2], sacc[f][3]));
    }
    nm0 = fmaxf(nm0, __shfl_xor_sync(0xffffffffu, nm0, 1));
    nm0 = fmaxf(nm0, __shfl_xor_sync(0xffffffffu, nm0, 2));
    nm1 = fmaxf(nm1, __shfl_xor_sync(0xffffffffu, nm1, 1));
    nm1 = fmaxf(nm1, __shfl_xor_sync(0xffffffffu, nm1, 2));
    const float a0 = __expf(m0 - nm0);
    const float a1 = __expf(m1 - nm1);
    m0 = nm0; m1 = nm1;
    lsum0 *= a0; lsum1 *= a1;
#pragma unroll
    for (int f = 0; f < 8; ++f) {
      oacc[f][0] *= a0; oacc[f][1] *= a0;
      oacc[f][2] *= a1; oacc[f][3] *= a1;
    }
    float rs0 = 0.0f, rs1 = 0.0f;
#pragma unroll
    for (int f = 0; f < 16; ++f) {
      sacc[f][0] = __expf(sacc[f][0] - m0);
      sacc[f][1] = __expf(sacc[f][1] - m0);
      sacc[f][2] = __expf(sacc[f][2] - m1);
      sacc[f][3] = __expf(sacc[f][3] - m1);
      rs0 += sacc[f][0] + sacc[f][1];
      rs1 += sacc[f][2] + sacc[f][3];
    }
    rs0 += __shfl_xor_sync(0xffffffffu, rs0, 1);
    rs0 += __shfl_xor_sync(0xffffffffu, rs0, 2);
    rs1 += __shfl_xor_sync(0xffffffffu, rs1, 1);
    rs1 += __shfl_xor_sync(0xffffffffu, rs1, 2);
    lsum0 += rs0; lsum1 += rs1;

    // ---- O += P V (P split x3, V via ldmatrix.trans) ----
#pragma unroll
    for (int kc2 = 0; kc2 < 8; ++kc2) {
      const float* f0 = sacc[2 * kc2];
      const float* f1 = sacc[2 * kc2 + 1];
      uint32_t ph[4], pl[4];
      split2(f0[0], f0[1], ph[0], pl[0]);
      split2(f0[2], f0[3], ph[1], pl[1]);
      split2(f1[0], f1[1], ph[2], pl[2]);
      split2(f1[2], f1[3], ph[3], pl[3]);
#pragma unroll
      for (int vg = 0; vg < 4; ++vg) {
        uint32_t vh4[4], vl4[4];
        const uint32_t vo = offV + (uint32_t)(kc2 * 16 * FD * 2) + vg * 32;
        ldmx4t(vh4, stg + TILE_E * 4 + vo);
        ldmx4t(vl4, stg + TILE_E * 6 + vo);
        mma16816(oacc[2 * vg], ph, &vh4[0]);
        mma16816(oacc[2 * vg], ph, &vl4[0]);
        mma16816(oacc[2 * vg], pl, &vh4[0]);
        mma16816(oacc[2 * vg + 1], ph, &vh4[2]);
        mma16816(oacc[2 * vg + 1], ph, &vl4[2]);
        mma16816(oacc[2 * vg + 1], pl, &vh4[2]);
      }
    }
  }

  // ---- epilogue: O /= l, store fp32 ----
  const float inv0 = 1.0f / lsum0;
  const float inv1 = 1.0f / lsum1;
  float* Ob = Og + (size_t)b * S_LEN * DMODEL + h * DKHEAD;
  const int gr0 = qt * 128 + wid * 16 + grp;
#pragma unroll
  for (int f = 0; f < 8; ++f) {
    const int col = f * 8 + tig * 2;
    *(float2*)(Ob + (size_t)gr0 * DMODEL + col) =
        make_float2(oacc[f][0] * inv0, oacc[f][1] * inv0);
    *(float2*)(Ob + (size_t)(gr0 + 8) * DMODEL + col) =
        make_float2(oacc[f][2] * inv1, oacc[f][3] * inv1);
  }
}

// ---------------------------------------------------------------------------
// Driver
// ---------------------------------------------------------------------------
extern "C" void kernel_launch(void* const* d_in, const int* in_sizes, int n_in,
                              void* d_out, int out_size) {
  (void)in_sizes; (void)n_in; (void)out_size;
  const float* q  = (const float*)d_in[0];
  const float* k  = (const float*)d_in[1];
  const float* v  = (const float*)d_in[2];
  // d_in[3] = mask: tril by construction; causal logic applied directly.
  const float* wq = (const float*)d_in[4];
  const float* bq = (const float*)d_in[5];
  const float* wk = (const float*)d_in[6];
  const float* bk = (const float*)d_in[7];
  const float* wv = (const float*)d_in[8];
  const float* bv = (const float*)d_in[9];
  const float* wo = (const float*)d_in[10];
  const float* bo = (const float*)d_in[11];
  float* out = (float*)d_out;

  float* pO;
  cudaGetSymbolAddress((void**)&pO, g_O);
  __nv_bfloat16 *pQh, *pQl, *pKh, *pKl, *pVh, *pVl;
  cudaGetSymbolAddress((void**)&pQh, g_Qh);
  cudaGetSymbolAddress((void**)&pQl, g_Ql);
  cudaGetSymbolAddress((void**)&pKh, g_Kh);
  cudaGetSymbolAddress((void**)&pKl, g_Kl);
  cudaGetSymbolAddress((void**)&pVh, g_Vh);
  cudaGetSymbolAddress((void**)&pVl, g_Vl);

  cudaFuncSetAttribute(flash_attn, cudaFuncAttributeMaxDynamicSharedMemorySize,
                       FLASH_SMEM);

  const dim3 gproj(DMODEL / 128, M_ROWS / 128);   // (8, 32)
  gemm_mma<true><<<gproj, 256>>>(q, wq, bq, nullptr, pQh, pQl);
  gemm_mma<true><<<gproj, 256>>>(k, wk, bk, nullptr, pKh, pKl);
  gemm_mma<true><<<gproj, 256>>>(v, wv, bv, nullptr, pVh, pVl);

  flash_attn<<<dim3(S_LEN / 128, BATCH * NHEAD), 256, FLASH_SMEM>>>(
      pQh, pQl, pKh, pKl, pVh, pVl, pO);

  gemm_mma<false><<<gproj, 256>>>(pO, wo, bo, out, nullptr, nullptr);
}